// round 1
// baseline (speedup 1.0000x reference)
#include <cuda_runtime.h>
#include <math.h>

#define BB 4
#define SS 2048
#define DD 512
#define HH 8
#define HDIM 64
#define NT (BB*SS)          // 8192 tokens
#define QKVD (3*DD)         // 1536

// ---- scratch (no allocations allowed) ----
__device__ float g_xn [NT*DD];        // 16 MB
__device__ float g_qkv[NT*QKVD];      // 48 MB
__device__ float g_att[NT*DD];        // 16 MB
__device__ float g_xr [NT*DD];        // 16 MB
__device__ float g_hid[NT*(DD/2)];    //  8 MB

// ============================================================
// 1) conditional LayerNorm  (one block per token, 128 threads)
// ============================================================
__global__ __launch_bounds__(128)
void ln_kernel(const float* __restrict__ x, const int* __restrict__ gt,
               const float* __restrict__ tfg, const float* __restrict__ tfb,
               const float* __restrict__ tgg, const float* __restrict__ tgb) {
    int t = blockIdx.x;
    int tid = threadIdx.x;                   // 0..127, 4 floats each
    const float4 v = ((const float4*)(x + (size_t)t*DD))[tid];
    float s  = v.x+v.y+v.z+v.w;
    float sq = v.x*v.x+v.y*v.y+v.z*v.z+v.w*v.w;
    #pragma unroll
    for (int o=16;o;o>>=1){ s += __shfl_xor_sync(~0u,s,o); sq += __shfl_xor_sync(~0u,sq,o); }
    __shared__ float sh[8];
    int w = tid>>5, l = tid&31;
    if (l==0){ sh[w]=s; sh[4+w]=sq; }
    __syncthreads();
    if (tid==0){
        float S=sh[0]+sh[1]+sh[2]+sh[3], Q=sh[4]+sh[5]+sh[6]+sh[7];
        float mu = S/(float)DD;
        float var = Q/(float)DD - mu*mu;
        sh[0]=mu; sh[1]=rsqrtf(var + 1e-5f);
    }
    __syncthreads();
    float mu = sh[0], rs = sh[1];
    int g = gt[t];
    float4 out;
    if (g==0 || g==1){
        const float* gp = (g==0)? tfg : tgg;
        const float* bp = (g==0)? tfb : tgb;
        float4 gv = ((const float4*)gp)[tid];
        float4 bv = ((const float4*)bp)[tid];
        out.x = (v.x-mu)*rs*gv.x + bv.x;
        out.y = (v.y-mu)*rs*gv.y + bv.y;
        out.z = (v.z-mu)*rs*gv.z + bv.z;
        out.w = (v.w-mu)*rs*gv.w + bv.w;
    } else {
        out = v;
    }
    ((float4*)(g_xn + (size_t)t*DD))[tid] = out;
}

// ============================================================
// 2) NT-GEMM: C[M,N] = A[M,K] * B[N,K]^T + bias, 64x64 tiles.
//    EPI: 0 = bias only, 1 = + residual, 2 = SiLU(bias+acc)
// ============================================================
template<int EPI>
__global__ __launch_bounds__(256)
void gemm64(const float* __restrict__ A, const float* __restrict__ B,
            const float* __restrict__ bias, const float* __restrict__ res,
            float* __restrict__ C, int N, int K) {
    __shared__ float As[16][68];
    __shared__ float Bs[16][68];
    int tid = threadIdx.x;
    int tx = tid & 15, ty = tid >> 4;
    int m0 = blockIdx.y * 64, n0 = blockIdx.x * 64;
    int lr = tid >> 2;          // 0..63 row within tile
    int lq = tid & 3;           // which float4 (k-quad)
    float acc[4][4] = {};
    for (int k0 = 0; k0 < K; k0 += 16) {
        float4 av = *(const float4*)(A + (size_t)(m0+lr)*K + k0 + lq*4);
        float4 bv = *(const float4*)(B + (size_t)(n0+lr)*K + k0 + lq*4);
        As[lq*4+0][lr]=av.x; As[lq*4+1][lr]=av.y; As[lq*4+2][lr]=av.z; As[lq*4+3][lr]=av.w;
        Bs[lq*4+0][lr]=bv.x; Bs[lq*4+1][lr]=bv.y; Bs[lq*4+2][lr]=bv.z; Bs[lq*4+3][lr]=bv.w;
        __syncthreads();
        #pragma unroll
        for (int kk=0;kk<16;kk++){
            float4 a = *(const float4*)&As[kk][ty*4];
            float4 b = *(const float4*)&Bs[kk][tx*4];
            acc[0][0]+=a.x*b.x; acc[0][1]+=a.x*b.y; acc[0][2]+=a.x*b.z; acc[0][3]+=a.x*b.w;
            acc[1][0]+=a.y*b.x; acc[1][1]+=a.y*b.y; acc[1][2]+=a.y*b.z; acc[1][3]+=a.y*b.w;
            acc[2][0]+=a.z*b.x; acc[2][1]+=a.z*b.y; acc[2][2]+=a.z*b.z; acc[2][3]+=a.z*b.w;
            acc[3][0]+=a.w*b.x; acc[3][1]+=a.w*b.y; acc[3][2]+=a.w*b.z; acc[3][3]+=a.w*b.w;
        }
        __syncthreads();
    }
    float4 bv = *(const float4*)(bias + n0 + tx*4);
    #pragma unroll
    for (int i=0;i<4;i++){
        int m = m0 + ty*4 + i;
        float4 c;
        c.x = acc[i][0] + bv.x;
        c.y = acc[i][1] + bv.y;
        c.z = acc[i][2] + bv.z;
        c.w = acc[i][3] + bv.w;
        if (EPI == 1) {
            float4 r = *(const float4*)(res + (size_t)m*N + n0 + tx*4);
            c.x += r.x; c.y += r.y; c.z += r.z; c.w += r.w;
        }
        if (EPI == 2) {
            c.x = c.x / (1.f + __expf(-c.x));
            c.y = c.y / (1.f + __expf(-c.y));
            c.z = c.z / (1.f + __expf(-c.z));
            c.w = c.w / (1.f + __expf(-c.w));
        }
        *(float4*)(C + (size_t)m*N + n0 + tx*4) = c;
    }
}

// ============================================================
// 3) attention: 1 warp per query, 4 warps/block share K/V tiles
// ============================================================
__global__ __launch_bounds__(128)
void attn_kernel() {
    __shared__ float Ks[32][68];
    __shared__ float Vs[32][68];
    __shared__ float qs[4][64];
    const float* qkv = g_qkv;
    int tid = threadIdx.x;
    int w = tid >> 5, lane = tid & 31;
    int gq = blockIdx.x * 4 + w;            // global query id over (b,h,s)
    int b = gq >> 14;
    int h = (gq >> 11) & 7;
    int s = gq & 2047;
    const float* qp = qkv + (size_t)(b*SS+s)*QKVD + h*HDIM;
    qs[w][lane]      = qp[lane];
    qs[w][lane+32]   = qp[lane+32];
    size_t kbase = (size_t)b*SS*QKVD + DD   + h*HDIM;   // K offset of this (b,h)
    size_t vbase = (size_t)b*SS*QKVD + 2*DD + h*HDIM;   // V offset
    float mrun = -1e30f, lrun = 0.f;
    float oa[64];
    #pragma unroll
    for (int d=0; d<64; d++) oa[d] = 0.f;
    int fr = tid >> 4;       // 0..7  (row group for tile load)
    int fc = tid & 15;       // float4 column
    for (int kt = 0; kt < SS/32; kt++) {
        __syncthreads();
        #pragma unroll
        for (int p=0;p<4;p++){
            int r = fr + p*8;
            size_t rowoff = (size_t)(kt*32 + r) * QKVD;
            *(float4*)&Ks[r][fc*4] = *(const float4*)(qkv + kbase + rowoff + fc*4);
            *(float4*)&Vs[r][fc*4] = *(const float4*)(qkv + vbase + rowoff + fc*4);
        }
        __syncthreads();
        // this lane handles key (kt*32 + lane)
        float dot = 0.f;
        #pragma unroll
        for (int d4=0; d4<16; d4++){
            float4 kk = *(const float4*)&Ks[lane][d4*4];
            float4 qq = *(const float4*)&qs[w][d4*4];
            dot += kk.x*qq.x + kk.y*qq.y + kk.z*qq.z + kk.w*qq.w;
        }
        dot *= 0.125f;                       // 1/sqrt(64)
        float nm = fmaxf(mrun, dot);
        float sc = __expf(mrun - nm);
        float pv = __expf(dot  - nm);
        lrun = lrun * sc + pv;
        mrun = nm;
        #pragma unroll
        for (int d4=0; d4<16; d4++){
            float4 vv = *(const float4*)&Vs[lane][d4*4];
            oa[d4*4+0] = oa[d4*4+0]*sc + pv*vv.x;
            oa[d4*4+1] = oa[d4*4+1]*sc + pv*vv.y;
            oa[d4*4+2] = oa[d4*4+2]*sc + pv*vv.z;
            oa[d4*4+3] = oa[d4*4+3]*sc + pv*vv.w;
        }
    }
    // merge 32 lanes (each holds a disjoint key subset)
    #pragma unroll
    for (int off=16; off; off>>=1){
        float om = __shfl_xor_sync(~0u, mrun, off);
        float ol = __shfl_xor_sync(~0u, lrun, off);
        float nm = fmaxf(mrun, om);
        float sa = __expf(mrun - nm);
        float sb = __expf(om   - nm);
        lrun = lrun*sa + ol*sb;
        mrun = nm;
        #pragma unroll
        for (int d=0; d<64; d++){
            float o2 = __shfl_xor_sync(~0u, oa[d], off);
            oa[d] = oa[d]*sa + o2*sb;
        }
    }
    float inv = 1.f / lrun;
    float* op = g_att + (size_t)(b*SS+s)*DD + h*HDIM;
    #pragma unroll
    for (int d=0; d<64; d++)
        if (lane == (d & 31)) op[d] = oa[d] * inv;
}

// ============================================================
// 4) gate: strength = sigmoid(h . w2 + b2); out = xr * strength
// ============================================================
__global__ __launch_bounds__(128)
void gate_kernel(const float* __restrict__ w2, const float* __restrict__ b2,
                 float* __restrict__ out) {
    int t = blockIdx.x;
    int tid = threadIdx.x;
    const float* hp = g_hid + (size_t)t*(DD/2);
    float part = hp[tid]*w2[tid] + hp[tid+128]*w2[tid+128];
    #pragma unroll
    for (int o=16;o;o>>=1) part += __shfl_xor_sync(~0u, part, o);
    __shared__ float sh[4];
    int w = tid>>5, l = tid&31;
    if (l==0) sh[w] = part;
    __syncthreads();
    float tot = sh[0]+sh[1]+sh[2]+sh[3];
    float sgate = 1.f / (1.f + __expf(-(tot + b2[0])));
    float4 xv = ((const float4*)(g_xr + (size_t)t*DD))[tid];
    float4 ov = { xv.x*sgate, xv.y*sgate, xv.z*sgate, xv.w*sgate };
    ((float4*)out)[(size_t)t*128 + tid] = ov;
}

// ============================================================
extern "C" void kernel_launch(void* const* d_in, const int* in_sizes, int n_in,
                              void* d_out, int out_size) {
    const float* x    = (const float*)d_in[0];
    const int*   gt   = (const int*)  d_in[1];
    const float* tf_g = (const float*)d_in[2];
    const float* tf_b = (const float*)d_in[3];
    const float* tg_g = (const float*)d_in[4];
    const float* tg_b = (const float*)d_in[5];
    const float* Wqkv = (const float*)d_in[6];
    const float* bqkv = (const float*)d_in[7];
    const float* Wo   = (const float*)d_in[8];
    const float* bo   = (const float*)d_in[9];
    const float* W1   = (const float*)d_in[10];
    const float* b1   = (const float*)d_in[11];
    const float* w2   = (const float*)d_in[12];
    const float* b2   = (const float*)d_in[13];
    float* out = (float*)d_out;

    float *xn, *qkvp, *att, *xr, *hid;
    cudaGetSymbolAddress((void**)&xn,   g_xn);
    cudaGetSymbolAddress((void**)&qkvp, g_qkv);
    cudaGetSymbolAddress((void**)&att,  g_att);
    cudaGetSymbolAddress((void**)&xr,   g_xr);
    cudaGetSymbolAddress((void**)&hid,  g_hid);

    // 1) conditional LayerNorm -> g_xn
    ln_kernel<<<NT, 128>>>(x, gt, tf_g, tf_b, tg_g, tg_b);
    // 2) QKV projection: [8192,512] x [1536,512]^T -> g_qkv
    gemm64<0><<<dim3(QKVD/64, NT/64), 256>>>(xn, Wqkv, bqkv, nullptr, qkvp, QKVD, DD);
    // 3) attention -> g_att
    attn_kernel<<<(NT*HH)/4, 128>>>();
    // 4) out projection + residual -> g_xr
    gemm64<1><<<dim3(DD/64, NT/64), 256>>>(att, Wo, bo, xn, xr, DD, DD);
    // 5) gate hidden: silu(xr @ W1^T + b1) -> g_hid
    gemm64<2><<<dim3((DD/2)/64, NT/64), 256>>>(xr, W1, b1, nullptr, hid, DD/2, DD);
    // 6) strength + final scale -> out
    gate_kernel<<<NT, 128>>>(w2, b2, out);
}

// round 4
// speedup vs baseline: 2.9581x; 2.9581x over previous
#include <cuda_runtime.h>
#include <math.h>

#define BB 4
#define SS 2048
#define DD 512
#define HH 8
#define HDIM 64
#define NT (BB*SS)          // 8192 tokens
#define QKVD (3*DD)         // 1536

// ---- scratch (no allocations allowed) ----
__device__ float g_xn [NT*DD];        // 16 MB
__device__ float g_qkv[NT*QKVD];      // 48 MB
__device__ float g_att[NT*DD];        // 16 MB
__device__ float g_xr [NT*DD];        // 16 MB
__device__ float g_hid[NT*(DD/2)];    //  8 MB

// ---------- tf32 helpers ----------
__device__ __forceinline__ unsigned f2tf(float f){
    unsigned u; asm("cvt.rna.tf32.f32 %0, %1;" : "=r"(u) : "f"(f)); return u;
}
__device__ __forceinline__ void mma_tf32(float* c, const unsigned* a, const unsigned* b){
    asm volatile("mma.sync.aligned.m16n8k8.row.col.f32.tf32.tf32.f32 "
        "{%0,%1,%2,%3},{%4,%5,%6,%7},{%8,%9},{%0,%1,%2,%3};"
        : "+f"(c[0]), "+f"(c[1]), "+f"(c[2]), "+f"(c[3])
        : "r"(a[0]), "r"(a[1]), "r"(a[2]), "r"(a[3]), "r"(b[0]), "r"(b[1]));
}

// ============================================================
// 1) conditional LayerNorm  (one block per token, 128 threads)
// ============================================================
__global__ __launch_bounds__(128)
void ln_kernel(const float* __restrict__ x, const int* __restrict__ gt,
               const float* __restrict__ tfg, const float* __restrict__ tfb,
               const float* __restrict__ tgg, const float* __restrict__ tgb) {
    int t = blockIdx.x;
    int tid = threadIdx.x;
    const float4 v = ((const float4*)(x + (size_t)t*DD))[tid];
    float s  = v.x+v.y+v.z+v.w;
    float sq = v.x*v.x+v.y*v.y+v.z*v.z+v.w*v.w;
    #pragma unroll
    for (int o=16;o;o>>=1){ s += __shfl_xor_sync(~0u,s,o); sq += __shfl_xor_sync(~0u,sq,o); }
    __shared__ float sh[8];
    int w = tid>>5, l = tid&31;
    if (l==0){ sh[w]=s; sh[4+w]=sq; }
    __syncthreads();
    if (tid==0){
        float S=sh[0]+sh[1]+sh[2]+sh[3], Q=sh[4]+sh[5]+sh[6]+sh[7];
        float mu = S/(float)DD;
        float var = Q/(float)DD - mu*mu;
        sh[0]=mu; sh[1]=rsqrtf(var + 1e-5f);
    }
    __syncthreads();
    float mu = sh[0], rs = sh[1];
    int g = gt[t];
    float4 out;
    if (g==0 || g==1){
        const float* gp = (g==0)? tfg : tgg;
        const float* bp = (g==0)? tfb : tgb;
        float4 gv = ((const float4*)gp)[tid];
        float4 bv = ((const float4*)bp)[tid];
        out.x = (v.x-mu)*rs*gv.x + bv.x;
        out.y = (v.y-mu)*rs*gv.y + bv.y;
        out.z = (v.z-mu)*rs*gv.z + bv.z;
        out.w = (v.w-mu)*rs*gv.w + bv.w;
    } else {
        out = v;
    }
    ((float4*)(g_xn + (size_t)t*DD))[tid] = out;
}

// ============================================================
// 2) tf32 tensor-core GEMM: C[M,N] = A[M,K]·B[N,K]^T (+bias/epi)
//    BM=BN=64, BK=16, 128 threads (4 warps, 2x2, 32x32 each)
//    EPI: 0 = bias, 1 = bias+residual, 2 = SiLU(bias+acc)
// ============================================================
#define SP 20   // smem pitch (floats) for 16-wide K chunk, conflict-free frags
template<int EPI>
__global__ __launch_bounds__(128)
void gemm_tc(const float* __restrict__ A, const float* __restrict__ B,
             const float* __restrict__ bias, const float* __restrict__ res,
             float* __restrict__ C, int N, int K) {
    __shared__ unsigned As[64*SP];
    __shared__ unsigned Bs[64*SP];
    int tid = threadIdx.x;
    int w = tid>>5, lane = tid&31;
    int qr = lane>>2, qc = lane&3;
    int wy = w>>1, wx = w&1;
    int m0 = blockIdx.y*64, n0 = blockIdx.x*64;

    int lr = tid>>1, lh = tid&1;           // loader: row 0..63, half 0/1

    float acc[2][4][4];
    #pragma unroll
    for (int i=0;i<2;i++)
        #pragma unroll
        for (int j=0;j<4;j++)
            #pragma unroll
            for (int k=0;k<4;k++) acc[i][j][k]=0.f;

    for (int k0 = 0; k0 < K; k0 += 16) {
        const float* ap = A + (size_t)(m0+lr)*K + k0 + lh*8;
        const float* bp = B + (size_t)(n0+lr)*K + k0 + lh*8;
        float4 a0 = *(const float4*)ap;
        float4 a1 = *(const float4*)(ap+4);
        float4 b0 = *(const float4*)bp;
        float4 b1 = *(const float4*)(bp+4);
        unsigned* ad = &As[lr*SP + lh*8];
        unsigned* bd = &Bs[lr*SP + lh*8];
        ad[0]=f2tf(a0.x); ad[1]=f2tf(a0.y); ad[2]=f2tf(a0.z); ad[3]=f2tf(a0.w);
        ad[4]=f2tf(a1.x); ad[5]=f2tf(a1.y); ad[6]=f2tf(a1.z); ad[7]=f2tf(a1.w);
        bd[0]=f2tf(b0.x); bd[1]=f2tf(b0.y); bd[2]=f2tf(b0.z); bd[3]=f2tf(b0.w);
        bd[4]=f2tf(b1.x); bd[5]=f2tf(b1.y); bd[6]=f2tf(b1.z); bd[7]=f2tf(b1.w);
        __syncthreads();
        #pragma unroll
        for (int ks=0; ks<2; ks++) {
            int kb = ks*8;
            unsigned af[2][4], bf[4][2];
            #pragma unroll
            for (int mt=0; mt<2; mt++){
                int r = wy*32 + mt*16 + qr;
                af[mt][0] = As[r*SP + kb + qc];
                af[mt][1] = As[(r+8)*SP + kb + qc];
                af[mt][2] = As[r*SP + kb + qc + 4];
                af[mt][3] = As[(r+8)*SP + kb + qc + 4];
            }
            #pragma unroll
            for (int nt=0; nt<4; nt++){
                int r = wx*32 + nt*8 + qr;
                bf[nt][0] = Bs[r*SP + kb + qc];
                bf[nt][1] = Bs[r*SP + kb + qc + 4];
            }
            #pragma unroll
            for (int mt=0; mt<2; mt++)
                #pragma unroll
                for (int nt=0; nt<4; nt++)
                    mma_tf32(acc[mt][nt], af[mt], bf[nt]);
        }
        __syncthreads();
    }
    #pragma unroll
    for (int mt=0; mt<2; mt++){
        #pragma unroll
        for (int nt=0; nt<4; nt++){
            int gr = m0 + wy*32 + mt*16 + qr;
            int gc = n0 + wx*32 + nt*8 + 2*qc;
            float bx = bias[gc], by = bias[gc+1];
            float c0 = acc[mt][nt][0]+bx, c1 = acc[mt][nt][1]+by;
            float c2 = acc[mt][nt][2]+bx, c3 = acc[mt][nt][3]+by;
            if (EPI==1){
                const float* r0 = res + (size_t)gr*N + gc;
                const float* r1 = res + (size_t)(gr+8)*N + gc;
                c0 += r0[0]; c1 += r0[1]; c2 += r1[0]; c3 += r1[1];
            }
            if (EPI==2){
                c0 = c0/(1.f+__expf(-c0)); c1 = c1/(1.f+__expf(-c1));
                c2 = c2/(1.f+__expf(-c2)); c3 = c3/(1.f+__expf(-c3));
            }
            float2 v0 = {c0,c1}, v1 = {c2,c3};
            *(float2*)(C + (size_t)gr*N + gc)     = v0;
            *(float2*)(C + (size_t)(gr+8)*N + gc) = v1;
        }
    }
}

// ============================================================
// 3) flash attention, tf32 mma: 64 queries/block, 64-key tiles
//    4 warps; warp w owns query rows w*16..w*16+15
//    smem: Ks [64 keys][64 d] pitch 68 (reused as P), Vt [64 d][64 keys]
// ============================================================
#define KP 68
__global__ __launch_bounds__(128)
void attn_tc() {
    __shared__ unsigned Ks[64*KP];
    __shared__ unsigned Vt[64*KP];
    const float* qkv = g_qkv;
    int tid = threadIdx.x;
    int w = tid>>5, lane = tid&31;
    int qr = lane>>2, qc = lane&3;
    int bh = blockIdx.y;
    int b = bh>>3, h = bh&7;
    int q0 = blockIdx.x*64;
    size_t base = (size_t)b*SS*QKVD + (size_t)h*HDIM;
    int lr = tid>>1, lh = tid&1;    // loader: row 0..63, 32-col half

    // stage Q (pre-scaled by 1/sqrt(64)) into Ks: FULL 64 cols per row
    {
        const float* qp = qkv + base + (size_t)(q0+lr)*QKVD + lh*32;
        unsigned* d = &Ks[lr*KP + lh*32];
        #pragma unroll
        for (int j=0;j<8;j++){
            float4 t4 = *(const float4*)(qp + j*4);
            d[j*4+0]=f2tf(t4.x*0.125f); d[j*4+1]=f2tf(t4.y*0.125f);
            d[j*4+2]=f2tf(t4.z*0.125f); d[j*4+3]=f2tf(t4.w*0.125f);
        }
    }
    __syncthreads();
    unsigned qa[8][4];
    {
        int row = w*16 + qr;
        #pragma unroll
        for (int ks=0; ks<8; ks++){
            qa[ks][0] = Ks[row*KP + ks*8 + qc];
            qa[ks][1] = Ks[(row+8)*KP + ks*8 + qc];
            qa[ks][2] = Ks[row*KP + ks*8 + qc + 4];
            qa[ks][3] = Ks[(row+8)*KP + ks*8 + qc + 4];
        }
    }
    float o[8][4];
    #pragma unroll
    for (int nt=0; nt<8; nt++){ o[nt][0]=0.f;o[nt][1]=0.f;o[nt][2]=0.f;o[nt][3]=0.f; }
    float m0=-1e30f, m1=-1e30f, l0=0.f, l1=0.f;

    for (int kt=0; kt<SS/64; kt++){
        __syncthreads();
        { // load K tile [key][d] and V tile transposed [d][key] — full 64 cols
            const float* kp = qkv + base + DD + (size_t)(kt*64+lr)*QKVD + lh*32;
            unsigned* kd = &Ks[lr*KP + lh*32];
            #pragma unroll
            for (int j=0;j<8;j++){
                float4 t4 = *(const float4*)(kp + j*4);
                kd[j*4+0]=f2tf(t4.x); kd[j*4+1]=f2tf(t4.y);
                kd[j*4+2]=f2tf(t4.z); kd[j*4+3]=f2tf(t4.w);
            }
            const float* vp = kp + DD;
            #pragma unroll
            for (int j=0;j<8;j++){
                float4 t4 = *(const float4*)(vp + j*4);
                int dc = lh*32 + j*4;
                Vt[(dc+0)*KP + lr]=f2tf(t4.x); Vt[(dc+1)*KP + lr]=f2tf(t4.y);
                Vt[(dc+2)*KP + lr]=f2tf(t4.z); Vt[(dc+3)*KP + lr]=f2tf(t4.w);
            }
        }
        __syncthreads();
        // S = Q·K^T  (per warp: 16 x 64)
        float sacc[8][4];
        #pragma unroll
        for (int nt=0; nt<8; nt++){ sacc[nt][0]=0.f;sacc[nt][1]=0.f;sacc[nt][2]=0.f;sacc[nt][3]=0.f; }
        #pragma unroll
        for (int ks=0; ks<8; ks++){
            #pragma unroll
            for (int nt=0; nt<8; nt++){
                unsigned bf[2];
                bf[0] = Ks[(nt*8+qr)*KP + ks*8 + qc];
                bf[1] = Ks[(nt*8+qr)*KP + ks*8 + qc + 4];
                mma_tf32(sacc[nt], qa[ks], bf);
            }
        }
        __syncthreads();   // everyone done reading Ks -> safe to reuse as P
        // online softmax (rows r0=lane/4, r1=+8 of this warp's 16)
        float mx0=-1e30f, mx1=-1e30f;
        #pragma unroll
        for (int nt=0; nt<8; nt++){
            mx0 = fmaxf(mx0, fmaxf(sacc[nt][0], sacc[nt][1]));
            mx1 = fmaxf(mx1, fmaxf(sacc[nt][2], sacc[nt][3]));
        }
        mx0 = fmaxf(mx0, __shfl_xor_sync(~0u, mx0, 1));
        mx0 = fmaxf(mx0, __shfl_xor_sync(~0u, mx0, 2));
        mx1 = fmaxf(mx1, __shfl_xor_sync(~0u, mx1, 1));
        mx1 = fmaxf(mx1, __shfl_xor_sync(~0u, mx1, 2));
        float nm0 = fmaxf(m0, mx0), nm1 = fmaxf(m1, mx1);
        float a0 = __expf(m0 - nm0), a1 = __expf(m1 - nm1);
        float s0 = 0.f, s1 = 0.f;
        #pragma unroll
        for (int nt=0; nt<8; nt++){
            sacc[nt][0] = __expf(sacc[nt][0] - nm0);
            sacc[nt][1] = __expf(sacc[nt][1] - nm0);
            sacc[nt][2] = __expf(sacc[nt][2] - nm1);
            sacc[nt][3] = __expf(sacc[nt][3] - nm1);
            s0 += sacc[nt][0] + sacc[nt][1];
            s1 += sacc[nt][2] + sacc[nt][3];
        }
        s0 += __shfl_xor_sync(~0u, s0, 1); s0 += __shfl_xor_sync(~0u, s0, 2);
        s1 += __shfl_xor_sync(~0u, s1, 1); s1 += __shfl_xor_sync(~0u, s1, 2);
        l0 = l0*a0 + s0; l1 = l1*a1 + s1; m0 = nm0; m1 = nm1;
        #pragma unroll
        for (int nt=0; nt<8; nt++){
            o[nt][0]*=a0; o[nt][1]*=a0; o[nt][2]*=a1; o[nt][3]*=a1;
        }
        // write P (tf32) into Ks region, own rows only
        {
            int row = w*16 + qr;
            #pragma unroll
            for (int nt=0; nt<8; nt++){
                Ks[row*KP + nt*8 + 2*qc]       = f2tf(sacc[nt][0]);
                Ks[row*KP + nt*8 + 2*qc + 1]   = f2tf(sacc[nt][1]);
                Ks[(row+8)*KP + nt*8 + 2*qc]   = f2tf(sacc[nt][2]);
                Ks[(row+8)*KP + nt*8 + 2*qc+1] = f2tf(sacc[nt][3]);
            }
        }
        __syncwarp();
        // O += P·V  (A = P from smem, B = V from transposed smem)
        {
            int row = w*16 + qr;
            #pragma unroll
            for (int ks=0; ks<8; ks++){
                unsigned pa[4];
                pa[0] = Ks[row*KP + ks*8 + qc];
                pa[1] = Ks[(row+8)*KP + ks*8 + qc];
                pa[2] = Ks[row*KP + ks*8 + qc + 4];
                pa[3] = Ks[(row+8)*KP + ks*8 + qc + 4];
                #pragma unroll
                for (int nt=0; nt<8; nt++){
                    unsigned bf[2];
                    bf[0] = Vt[(nt*8+qr)*KP + ks*8 + qc];
                    bf[1] = Vt[(nt*8+qr)*KP + ks*8 + qc + 4];
                    mma_tf32(o[nt], pa, bf);
                }
            }
        }
    }
    float i0 = 1.f/l0, i1 = 1.f/l1;
    int sr = q0 + w*16 + qr;
    float* op = g_att + (size_t)(b*SS + sr)*DD + h*HDIM;
    #pragma unroll
    for (int nt=0; nt<8; nt++){
        float2 v0 = { o[nt][0]*i0, o[nt][1]*i0 };
        float2 v1 = { o[nt][2]*i1, o[nt][3]*i1 };
        *(float2*)(op + nt*8 + 2*qc)          = v0;
        *(float2*)(op + 8*DD + nt*8 + 2*qc)   = v1;
    }
}

// ============================================================
// 4) gate: strength = sigmoid(h . w2 + b2); out = xr * strength
// ============================================================
__global__ __launch_bounds__(128)
void gate_kernel(const float* __restrict__ w2, const float* __restrict__ b2,
                 float* __restrict__ out) {
    int t = blockIdx.x;
    int tid = threadIdx.x;
    const float* hp = g_hid + (size_t)t*(DD/2);
    float part = hp[tid]*w2[tid] + hp[tid+128]*w2[tid+128];
    #pragma unroll
    for (int o=16;o;o>>=1) part += __shfl_xor_sync(~0u, part, o);
    __shared__ float sh[4];
    int w = tid>>5, l = tid&31;
    if (l==0) sh[w] = part;
    __syncthreads();
    float tot = sh[0]+sh[1]+sh[2]+sh[3];
    float sgate = 1.f / (1.f + __expf(-(tot + b2[0])));
    float4 xv = ((const float4*)(g_xr + (size_t)t*DD))[tid];
    float4 ov = { xv.x*sgate, xv.y*sgate, xv.z*sgate, xv.w*sgate };
    ((float4*)out)[(size_t)t*128 + tid] = ov;
}

// ============================================================
extern "C" void kernel_launch(void* const* d_in, const int* in_sizes, int n_in,
                              void* d_out, int out_size) {
    const float* x    = (const float*)d_in[0];
    const int*   gt   = (const int*)  d_in[1];
    const float* tf_g = (const float*)d_in[2];
    const float* tf_b = (const float*)d_in[3];
    const float* tg_g = (const float*)d_in[4];
    const float* tg_b = (const float*)d_in[5];
    const float* Wqkv = (const float*)d_in[6];
    const float* bqkv = (const float*)d_in[7];
    const float* Wo   = (const float*)d_in[8];
    const float* bo   = (const float*)d_in[9];
    const float* W1   = (const float*)d_in[10];
    const float* b1   = (const float*)d_in[11];
    const float* w2   = (const float*)d_in[12];
    const float* b2   = (const float*)d_in[13];
    float* out = (float*)d_out;

    float *xn, *qkvp, *att, *xr, *hid;
    cudaGetSymbolAddress((void**)&xn,   g_xn);
    cudaGetSymbolAddress((void**)&qkvp, g_qkv);
    cudaGetSymbolAddress((void**)&att,  g_att);
    cudaGetSymbolAddress((void**)&xr,   g_xr);
    cudaGetSymbolAddress((void**)&hid,  g_hid);

    // 1) conditional LayerNorm -> g_xn
    ln_kernel<<<NT, 128>>>(x, gt, tf_g, tf_b, tg_g, tg_b);
    // 2) QKV projection -> g_qkv
    gemm_tc<0><<<dim3(QKVD/64, NT/64), 128>>>(xn, Wqkv, bqkv, nullptr, qkvp, QKVD, DD);
    // 3) flash attention -> g_att
    attn_tc<<<dim3(SS/64, BB*HH), 128>>>();
    // 4) out projection + residual -> g_xr
    gemm_tc<1><<<dim3(DD/64, NT/64), 128>>>(att, Wo, bo, xn, xr, DD, DD);
    // 5) gate hidden: silu(xr @ W1^T + b1) -> g_hid
    gemm_tc<2><<<dim3((DD/2)/64, NT/64), 128>>>(xr, W1, b1, nullptr, hid, DD/2, DD);
    // 6) strength + final scale -> out
    gate_kernel<<<NT, 128>>>(w2, b2, out);
}

// round 5
// speedup vs baseline: 11.5527x; 3.9054x over previous
#include <cuda_runtime.h>
#include <cuda_bf16.h>
#include <math.h>

#define BB 4
#define SS 2048
#define DD 512
#define HH 8
#define HDIM 64
#define NT (BB*SS)          // 8192 tokens
#define QKVD (3*DD)         // 1536

// ---- scratch (no allocations allowed) ----
__device__ float          g_xn [NT*DD];          // fp32 (residual path)
__device__ __nv_bfloat16  g_xnh[NT*DD];          // bf16 GEMM input
__device__ __nv_bfloat16  g_qkv[NT*QKVD];        // bf16
__device__ __nv_bfloat16  g_att[NT*DD];          // bf16
__device__ float          g_xr [NT*DD];          // fp32
__device__ __nv_bfloat16  g_xrh[NT*DD];          // bf16
__device__ float          g_hid[NT*(DD/2)];      // fp32
__device__ __nv_bfloat16  g_wqkvh[QKVD*DD];
__device__ __nv_bfloat16  g_woh [DD*DD];
__device__ __nv_bfloat16  g_w1h [(DD/2)*DD];

// ---------- mma / ldmatrix helpers ----------
__device__ __forceinline__ void mma_bf16(float* c, const unsigned* a, const unsigned* b){
    asm volatile("mma.sync.aligned.m16n8k16.row.col.f32.bf16.bf16.f32 "
        "{%0,%1,%2,%3},{%4,%5,%6,%7},{%8,%9},{%0,%1,%2,%3};"
        : "+f"(c[0]), "+f"(c[1]), "+f"(c[2]), "+f"(c[3])
        : "r"(a[0]), "r"(a[1]), "r"(a[2]), "r"(a[3]), "r"(b[0]), "r"(b[1]));
}
__device__ __forceinline__ void ldsm4(unsigned& r0, unsigned& r1, unsigned& r2, unsigned& r3, const void* p){
    unsigned a = (unsigned)__cvta_generic_to_shared(p);
    asm volatile("ldmatrix.sync.aligned.m8n8.x4.shared.b16 {%0,%1,%2,%3}, [%4];"
        : "=r"(r0), "=r"(r1), "=r"(r2), "=r"(r3) : "r"(a));
}
__device__ __forceinline__ void ldsm4t(unsigned& r0, unsigned& r1, unsigned& r2, unsigned& r3, const void* p){
    unsigned a = (unsigned)__cvta_generic_to_shared(p);
    asm volatile("ldmatrix.sync.aligned.m8n8.x4.trans.shared.b16 {%0,%1,%2,%3}, [%4];"
        : "=r"(r0), "=r"(r1), "=r"(r2), "=r"(r3) : "r"(a));
}
__device__ __forceinline__ unsigned pack_bf(float a, float b){
    __nv_bfloat162 h = __floats2bfloat162_rn(a, b);
    return *(unsigned*)&h;
}

// ============================================================
// 0) fp32 -> bf16 weight conversion
// ============================================================
__global__ __launch_bounds__(256)
void cvt_bf(const float4* __restrict__ src, uint2* __restrict__ dst, int n4){
    int i = blockIdx.x*256 + threadIdx.x;
    if (i < n4){
        float4 v = src[i];
        dst[i] = make_uint2(pack_bf(v.x, v.y), pack_bf(v.z, v.w));
    }
}

// ============================================================
// 1) conditional LayerNorm (writes fp32 + bf16 copies)
// ============================================================
__global__ __launch_bounds__(128)
void ln_kernel(const float* __restrict__ x, const int* __restrict__ gt,
               const float* __restrict__ tfg, const float* __restrict__ tfb,
               const float* __restrict__ tgg, const float* __restrict__ tgb) {
    int t = blockIdx.x;
    int tid = threadIdx.x;
    const float4 v = ((const float4*)(x + (size_t)t*DD))[tid];
    float s  = v.x+v.y+v.z+v.w;
    float sq = v.x*v.x+v.y*v.y+v.z*v.z+v.w*v.w;
    #pragma unroll
    for (int o=16;o;o>>=1){ s += __shfl_xor_sync(~0u,s,o); sq += __shfl_xor_sync(~0u,sq,o); }
    __shared__ float sh[8];
    int w = tid>>5, l = tid&31;
    if (l==0){ sh[w]=s; sh[4+w]=sq; }
    __syncthreads();
    if (tid==0){
        float S=sh[0]+sh[1]+sh[2]+sh[3], Q=sh[4]+sh[5]+sh[6]+sh[7];
        float mu = S/(float)DD;
        float var = Q/(float)DD - mu*mu;
        sh[0]=mu; sh[1]=rsqrtf(var + 1e-5f);
    }
    __syncthreads();
    float mu = sh[0], rs = sh[1];
    int g = gt[t];
    float4 out;
    if (g==0 || g==1){
        const float* gp = (g==0)? tfg : tgg;
        const float* bp = (g==0)? tfb : tgb;
        float4 gv = ((const float4*)gp)[tid];
        float4 bv = ((const float4*)bp)[tid];
        out.x = (v.x-mu)*rs*gv.x + bv.x;
        out.y = (v.y-mu)*rs*gv.y + bv.y;
        out.z = (v.z-mu)*rs*gv.z + bv.z;
        out.w = (v.w-mu)*rs*gv.w + bv.w;
    } else {
        out = v;
    }
    ((float4*)(g_xn + (size_t)t*DD))[tid] = out;
    ((uint2*)(g_xnh + (size_t)t*DD))[tid] = make_uint2(pack_bf(out.x,out.y), pack_bf(out.z,out.w));
}

// ============================================================
// 2) bf16 tensor-core GEMM: C[M,N] = A[M,K]·B[N,K]^T (+bias/epi)
//    128x128 block, 256 threads (8 warps, 4x2, 32x64 warp tile), BK=32
//    EPI: 0 = bias -> Cb(bf16); 1 = bias+res -> Cf(fp32)+Cb(bf16);
//         2 = SiLU(bias+acc) -> Cf(fp32)
// ============================================================
#define GP 40   // smem pitch in halfs (80B, conflict-free LDSM)
template<int EPI>
__global__ __launch_bounds__(256)
void gemm_bf(const __nv_bfloat16* __restrict__ A, const __nv_bfloat16* __restrict__ B,
             const float* __restrict__ bias, const float* __restrict__ res,
             float* __restrict__ Cf, __nv_bfloat16* __restrict__ Cb, int N, int K) {
    __shared__ __nv_bfloat16 As[128*GP];
    __shared__ __nv_bfloat16 Bs[128*GP];
    int tid = threadIdx.x;
    int w = tid>>5, lane = tid&31;
    int qr = lane>>2, qc = lane&3;
    int wy = w>>1, wx = w&1;
    int m0 = blockIdx.y*128, n0 = blockIdx.x*128;
    int lr = tid>>1, lh = tid&1;           // loader: row 0..127, 32B half
    int lmr = lane & 15, lmc = lane >> 4;  // ldmatrix addressing

    float acc[2][8][4];
    #pragma unroll
    for (int i=0;i<2;i++)
        #pragma unroll
        for (int j=0;j<8;j++)
            #pragma unroll
            for (int k=0;k<4;k++) acc[i][j][k]=0.f;

    for (int k0 = 0; k0 < K; k0 += 32) {
        const uint4* ap = (const uint4*)(A + (size_t)(m0+lr)*K + k0 + lh*16);
        const uint4* bp = (const uint4*)(B + (size_t)(n0+lr)*K + k0 + lh*16);
        uint4 a0 = ap[0], a1 = ap[1];
        uint4 b0 = bp[0], b1 = bp[1];
        *(uint4*)&As[lr*GP + lh*16]     = a0;
        *(uint4*)&As[lr*GP + lh*16 + 8] = a1;
        *(uint4*)&Bs[lr*GP + lh*16]     = b0;
        *(uint4*)&Bs[lr*GP + lh*16 + 8] = b1;
        __syncthreads();
        #pragma unroll
        for (int ks=0; ks<2; ks++) {
            int kb = ks*16;
            unsigned af[2][4], bf[8][2];
            #pragma unroll
            for (int mt=0; mt<2; mt++)
                ldsm4(af[mt][0], af[mt][1], af[mt][2], af[mt][3],
                      &As[(wy*32 + mt*16 + lmr)*GP + kb + lmc*8]);
            #pragma unroll
            for (int ng=0; ng<4; ng++){
                unsigned r0,r1,r2,r3;
                ldsm4(r0,r1,r2,r3, &Bs[(wx*64 + ng*16 + lmr)*GP + kb + lmc*8]);
                bf[2*ng  ][0]=r0; bf[2*ng  ][1]=r2;
                bf[2*ng+1][0]=r1; bf[2*ng+1][1]=r3;
            }
            #pragma unroll
            for (int mt=0; mt<2; mt++)
                #pragma unroll
                for (int nt=0; nt<8; nt++)
                    mma_bf16(acc[mt][nt], af[mt], bf[nt]);
        }
        __syncthreads();
    }
    #pragma unroll
    for (int mt=0; mt<2; mt++){
        #pragma unroll
        for (int nt=0; nt<8; nt++){
            int gr = m0 + wy*32 + mt*16 + qr;
            int gc = n0 + wx*64 + nt*8 + 2*qc;
            float bx = bias[gc], by = bias[gc+1];
            float c0 = acc[mt][nt][0]+bx, c1 = acc[mt][nt][1]+by;
            float c2 = acc[mt][nt][2]+bx, c3 = acc[mt][nt][3]+by;
            if (EPI==0){
                *(unsigned*)(Cb + (size_t)gr*N + gc)     = pack_bf(c0,c1);
                *(unsigned*)(Cb + (size_t)(gr+8)*N + gc) = pack_bf(c2,c3);
            }
            if (EPI==1){
                const float* r0 = res + (size_t)gr*N + gc;
                const float* r1 = res + (size_t)(gr+8)*N + gc;
                c0 += r0[0]; c1 += r0[1]; c2 += r1[0]; c3 += r1[1];
                float2 v0 = {c0,c1}, v1 = {c2,c3};
                *(float2*)(Cf + (size_t)gr*N + gc)     = v0;
                *(float2*)(Cf + (size_t)(gr+8)*N + gc) = v1;
                *(unsigned*)(Cb + (size_t)gr*N + gc)     = pack_bf(c0,c1);
                *(unsigned*)(Cb + (size_t)(gr+8)*N + gc) = pack_bf(c2,c3);
            }
            if (EPI==2){
                c0 = c0/(1.f+__expf(-c0)); c1 = c1/(1.f+__expf(-c1));
                c2 = c2/(1.f+__expf(-c2)); c3 = c3/(1.f+__expf(-c3));
                float2 v0 = {c0,c1}, v1 = {c2,c3};
                *(float2*)(Cf + (size_t)gr*N + gc)     = v0;
                *(float2*)(Cf + (size_t)(gr+8)*N + gc) = v1;
            }
        }
    }
}

// ============================================================
// 3) flash attention, bf16 mma + ldmatrix
//    64 queries/block, 64-key tiles, 4 warps (16 q rows each)
//    Ks [64 key][64 d] pitch 72 (reused as P), Vs [64 key][64 d] (trans-read)
// ============================================================
#define AP 72
__global__ __launch_bounds__(128)
void attn_bf() {
    __shared__ __nv_bfloat16 Ks[64*AP];
    __shared__ __nv_bfloat16 Vs[64*AP];
    const __nv_bfloat16* qkv = g_qkv;
    int tid = threadIdx.x;
    int w = tid>>5, lane = tid&31;
    int qr = lane>>2, qc = lane&3;
    int lmr = lane & 15, lmc = lane >> 4;
    int b = blockIdx.y>>3, h = blockIdx.y&7;
    int q0 = blockIdx.x*64;
    size_t base = (size_t)b*SS*QKVD + (size_t)h*HDIM;
    int lr = tid>>1, lh = tid&1;    // loader: row 0..63, 64B half

    // stage Q into Ks, pull frags to regs
    {
        const uint4* qp = (const uint4*)(qkv + base + (size_t)(q0+lr)*QKVD + lh*32);
        uint4 v0 = qp[0], v1 = qp[1], v2 = qp[2], v3 = qp[3];
        uint4* d = (uint4*)&Ks[lr*AP + lh*32];
        d[0]=v0; d[1]=v1; d[2]=v2; d[3]=v3;
    }
    __syncthreads();
    unsigned qa[4][4];
    #pragma unroll
    for (int kc=0; kc<4; kc++)
        ldsm4(qa[kc][0], qa[kc][1], qa[kc][2], qa[kc][3],
              &Ks[(w*16 + lmr)*AP + kc*16 + lmc*8]);

    float o[8][4];
    #pragma unroll
    for (int nt=0; nt<8; nt++){ o[nt][0]=0.f;o[nt][1]=0.f;o[nt][2]=0.f;o[nt][3]=0.f; }
    float m0=-1e30f, m1=-1e30f, l0=0.f, l1=0.f;

    for (int kt=0; kt<SS/64; kt++){
        __syncthreads();
        {   // load K tile and V tile, both [key][d]
            const uint4* kp = (const uint4*)(qkv + base + DD + (size_t)(kt*64+lr)*QKVD + lh*32);
            const uint4* vp = (const uint4*)(qkv + base + 2*DD + (size_t)(kt*64+lr)*QKVD + lh*32);
            uint4 k0 = kp[0], k1 = kp[1], k2 = kp[2], k3 = kp[3];
            uint4 v0 = vp[0], v1 = vp[1], v2 = vp[2], v3 = vp[3];
            uint4* kd = (uint4*)&Ks[lr*AP + lh*32];
            uint4* vd = (uint4*)&Vs[lr*AP + lh*32];
            kd[0]=k0; kd[1]=k1; kd[2]=k2; kd[3]=k3;
            vd[0]=v0; vd[1]=v1; vd[2]=v2; vd[3]=v3;
        }
        __syncthreads();
        // S = Q·K^T  (per warp: 16 x 64)
        float sacc[8][4];
        #pragma unroll
        for (int nt=0; nt<8; nt++){ sacc[nt][0]=0.f;sacc[nt][1]=0.f;sacc[nt][2]=0.f;sacc[nt][3]=0.f; }
        #pragma unroll
        for (int kc=0; kc<4; kc++){
            #pragma unroll
            for (int ng=0; ng<4; ng++){
                unsigned r0,r1,r2,r3;
                ldsm4(r0,r1,r2,r3, &Ks[(ng*16 + lmr)*AP + kc*16 + lmc*8]);
                unsigned bfa[2] = {r0, r2};
                unsigned bfb[2] = {r1, r3};
                mma_bf16(sacc[2*ng  ], qa[kc], bfa);
                mma_bf16(sacc[2*ng+1], qa[kc], bfb);
            }
        }
        __syncthreads();   // all warps done reading Ks -> safe to reuse as P
        // scale + online softmax
        float mx0=-1e30f, mx1=-1e30f;
        #pragma unroll
        for (int nt=0; nt<8; nt++){
            sacc[nt][0]*=0.125f; sacc[nt][1]*=0.125f; sacc[nt][2]*=0.125f; sacc[nt][3]*=0.125f;
            mx0 = fmaxf(mx0, fmaxf(sacc[nt][0], sacc[nt][1]));
            mx1 = fmaxf(mx1, fmaxf(sacc[nt][2], sacc[nt][3]));
        }
        mx0 = fmaxf(mx0, __shfl_xor_sync(~0u, mx0, 1));
        mx0 = fmaxf(mx0, __shfl_xor_sync(~0u, mx0, 2));
        mx1 = fmaxf(mx1, __shfl_xor_sync(~0u, mx1, 1));
        mx1 = fmaxf(mx1, __shfl_xor_sync(~0u, mx1, 2));
        float nm0 = fmaxf(m0, mx0), nm1 = fmaxf(m1, mx1);
        float a0 = __expf(m0 - nm0), a1 = __expf(m1 - nm1);
        float s0 = 0.f, s1 = 0.f;
        #pragma unroll
        for (int nt=0; nt<8; nt++){
            sacc[nt][0] = __expf(sacc[nt][0] - nm0);
            sacc[nt][1] = __expf(sacc[nt][1] - nm0);
            sacc[nt][2] = __expf(sacc[nt][2] - nm1);
            sacc[nt][3] = __expf(sacc[nt][3] - nm1);
            s0 += sacc[nt][0] + sacc[nt][1];
            s1 += sacc[nt][2] + sacc[nt][3];
        }
        s0 += __shfl_xor_sync(~0u, s0, 1); s0 += __shfl_xor_sync(~0u, s0, 2);
        s1 += __shfl_xor_sync(~0u, s1, 1); s1 += __shfl_xor_sync(~0u, s1, 2);
        l0 = l0*a0 + s0; l1 = l1*a1 + s1; m0 = nm0; m1 = nm1;
        #pragma unroll
        for (int nt=0; nt<8; nt++){
            o[nt][0]*=a0; o[nt][1]*=a0; o[nt][2]*=a1; o[nt][3]*=a1;
        }
        // write P (bf16) into Ks region, own warp rows only
        {
            int row = w*16 + qr;
            #pragma unroll
            for (int nt=0; nt<8; nt++){
                *(unsigned*)&Ks[row*AP + nt*8 + 2*qc]     = pack_bf(sacc[nt][0], sacc[nt][1]);
                *(unsigned*)&Ks[(row+8)*AP + nt*8 + 2*qc] = pack_bf(sacc[nt][2], sacc[nt][3]);
            }
        }
        __syncwarp();
        // O += P·V  (A = P via ldsm, B = V via ldsm.trans)
        #pragma unroll
        for (int kc=0; kc<4; kc++){
            unsigned pa[4];
            ldsm4(pa[0], pa[1], pa[2], pa[3],
                  &Ks[(w*16 + lmr)*AP + kc*16 + lmc*8]);
            #pragma unroll
            for (int ng=0; ng<4; ng++){
                unsigned r0,r1,r2,r3;
                ldsm4t(r0,r1,r2,r3,
                       &Vs[(kc*16 + ((lane>>3)&1)*8 + (lane&7))*AP + ng*16 + (lane>>4)*8]);
                unsigned bfa[2] = {r0, r1};
                unsigned bfb[2] = {r2, r3};
                mma_bf16(o[2*ng  ], pa, bfa);
                mma_bf16(o[2*ng+1], pa, bfb);
            }
        }
    }
    float i0 = 1.f/l0, i1 = 1.f/l1;
    int sr = q0 + w*16 + qr;
    __nv_bfloat16* op = g_att + (size_t)(b*SS + sr)*DD + h*HDIM;
    #pragma unroll
    for (int nt=0; nt<8; nt++){
        *(unsigned*)(op + nt*8 + 2*qc)        = pack_bf(o[nt][0]*i0, o[nt][1]*i0);
        *(unsigned*)(op + 8*DD + nt*8 + 2*qc) = pack_bf(o[nt][2]*i1, o[nt][3]*i1);
    }
}

// ============================================================
// 4) gate: strength = sigmoid(h . w2 + b2); out = xr * strength
// ============================================================
__global__ __launch_bounds__(128)
void gate_kernel(const float* __restrict__ w2, const float* __restrict__ b2,
                 float* __restrict__ out) {
    int t = blockIdx.x;
    int tid = threadIdx.x;
    const float* hp = g_hid + (size_t)t*(DD/2);
    float part = hp[tid]*w2[tid] + hp[tid+128]*w2[tid+128];
    #pragma unroll
    for (int o=16;o;o>>=1) part += __shfl_xor_sync(~0u, part, o);
    __shared__ float sh[4];
    int w = tid>>5, l = tid&31;
    if (l==0) sh[w] = part;
    __syncthreads();
    float tot = sh[0]+sh[1]+sh[2]+sh[3];
    float sgate = 1.f / (1.f + __expf(-(tot + b2[0])));
    float4 xv = ((const float4*)(g_xr + (size_t)t*DD))[tid];
    float4 ov = { xv.x*sgate, xv.y*sgate, xv.z*sgate, xv.w*sgate };
    ((float4*)out)[(size_t)t*128 + tid] = ov;
}

// ============================================================
extern "C" void kernel_launch(void* const* d_in, const int* in_sizes, int n_in,
                              void* d_out, int out_size) {
    const float* x    = (const float*)d_in[0];
    const int*   gt   = (const int*)  d_in[1];
    const float* tf_g = (const float*)d_in[2];
    const float* tf_b = (const float*)d_in[3];
    const float* tg_g = (const float*)d_in[4];
    const float* tg_b = (const float*)d_in[5];
    const float* Wqkv = (const float*)d_in[6];
    const float* bqkv = (const float*)d_in[7];
    const float* Wo   = (const float*)d_in[8];
    const float* bo   = (const float*)d_in[9];
    const float* W1   = (const float*)d_in[10];
    const float* b1   = (const float*)d_in[11];
    const float* w2   = (const float*)d_in[12];
    const float* b2   = (const float*)d_in[13];
    float* out = (float*)d_out;

    float *xn, *xr, *hid;
    __nv_bfloat16 *xnh, *qkvp, *att, *xrh, *wqkvh, *woh, *w1h;
    cudaGetSymbolAddress((void**)&xn,    g_xn);
    cudaGetSymbolAddress((void**)&xnh,   g_xnh);
    cudaGetSymbolAddress((void**)&qkvp,  g_qkv);
    cudaGetSymbolAddress((void**)&att,   g_att);
    cudaGetSymbolAddress((void**)&xr,    g_xr);
    cudaGetSymbolAddress((void**)&xrh,   g_xrh);
    cudaGetSymbolAddress((void**)&hid,   g_hid);
    cudaGetSymbolAddress((void**)&wqkvh, g_wqkvh);
    cudaGetSymbolAddress((void**)&woh,   g_woh);
    cudaGetSymbolAddress((void**)&w1h,   g_w1h);

    // 0) weight conversions fp32 -> bf16
    cvt_bf<<<(QKVD*DD/4 + 255)/256, 256>>>((const float4*)Wqkv, (uint2*)wqkvh, QKVD*DD/4);
    cvt_bf<<<(DD*DD/4 + 255)/256, 256>>>((const float4*)Wo, (uint2*)woh, DD*DD/4);
    cvt_bf<<<((DD/2)*DD/4 + 255)/256, 256>>>((const float4*)W1, (uint2*)w1h, (DD/2)*DD/4);
    // 1) conditional LayerNorm -> g_xn (fp32) + g_xnh (bf16)
    ln_kernel<<<NT, 128>>>(x, gt, tf_g, tf_b, tg_g, tg_b);
    // 2) QKV projection -> g_qkv (bf16)
    gemm_bf<0><<<dim3(QKVD/128, NT/128), 256>>>(xnh, wqkvh, bqkv, nullptr, nullptr, qkvp, QKVD, DD);
    // 3) flash attention -> g_att (bf16)
    attn_bf<<<dim3(SS/64, BB*HH), 128>>>();
    // 4) out projection + residual -> g_xr (fp32) + g_xrh (bf16)
    gemm_bf<1><<<dim3(DD/128, NT/128), 256>>>(att, woh, bo, xn, xr, xrh, DD, DD);
    // 5) gate hidden: silu(xr @ W1^T + b1) -> g_hid (fp32)
    gemm_bf<2><<<dim3((DD/2)/128, NT/128), 256>>>(xrh, w1h, b1, nullptr, hid, nullptr, DD/2, DD);
    // 6) strength + final scale -> out
    gate_kernel<<<NT, 128>>>(w2, b2, out);
}

// round 6
// speedup vs baseline: 12.9761x; 1.1232x over previous
#include <cuda_runtime.h>
#include <cuda_bf16.h>
#include <math.h>

#define BB 4
#define SS 2048
#define DD 512
#define HH 8
#define HDIM 64
#define NT (BB*SS)          // 8192 tokens
#define QKVD (3*DD)         // 1536

// ---- scratch (no allocations allowed) ----
__device__ float          g_xn [NT*DD];          // fp32 (residual path)
__device__ __nv_bfloat16  g_xnh[NT*DD];          // bf16 GEMM input
__device__ __nv_bfloat16  g_qkv[NT*QKVD];        // bf16
__device__ __nv_bfloat16  g_att[NT*DD];          // bf16
__device__ float          g_xr [NT*DD];          // fp32
__device__ __nv_bfloat16  g_xrh[NT*DD];          // bf16
__device__ float          g_hid[NT*(DD/2)];      // fp32
__device__ __nv_bfloat16  g_wqkvh[QKVD*DD];
__device__ __nv_bfloat16  g_woh [DD*DD];
__device__ __nv_bfloat16  g_w1h [(DD/2)*DD];

// ---------- mma / ldmatrix / cp.async helpers ----------
__device__ __forceinline__ void mma_bf16(float* c, const unsigned* a, const unsigned* b){
    asm volatile("mma.sync.aligned.m16n8k16.row.col.f32.bf16.bf16.f32 "
        "{%0,%1,%2,%3},{%4,%5,%6,%7},{%8,%9},{%0,%1,%2,%3};"
        : "+f"(c[0]), "+f"(c[1]), "+f"(c[2]), "+f"(c[3])
        : "r"(a[0]), "r"(a[1]), "r"(a[2]), "r"(a[3]), "r"(b[0]), "r"(b[1]));
}
__device__ __forceinline__ void ldsm4(unsigned& r0, unsigned& r1, unsigned& r2, unsigned& r3, const void* p){
    unsigned a = (unsigned)__cvta_generic_to_shared(p);
    asm volatile("ldmatrix.sync.aligned.m8n8.x4.shared.b16 {%0,%1,%2,%3}, [%4];"
        : "=r"(r0), "=r"(r1), "=r"(r2), "=r"(r3) : "r"(a));
}
__device__ __forceinline__ void ldsm4t(unsigned& r0, unsigned& r1, unsigned& r2, unsigned& r3, const void* p){
    unsigned a = (unsigned)__cvta_generic_to_shared(p);
    asm volatile("ldmatrix.sync.aligned.m8n8.x4.trans.shared.b16 {%0,%1,%2,%3}, [%4];"
        : "=r"(r0), "=r"(r1), "=r"(r2), "=r"(r3) : "r"(a));
}
__device__ __forceinline__ unsigned pack_bf(float a, float b){
    __nv_bfloat162 h = __floats2bfloat162_rn(a, b);
    return *(unsigned*)&h;
}
__device__ __forceinline__ void cpa16(void* dst, const void* src){
    unsigned d = (unsigned)__cvta_generic_to_shared(dst);
    asm volatile("cp.async.cg.shared.global [%0], [%1], 16;" :: "r"(d), "l"(src));
}
__device__ __forceinline__ void cpa_commit(){ asm volatile("cp.async.commit_group;" ::: "memory"); }
__device__ __forceinline__ void cpa_wait_all(){ asm volatile("cp.async.wait_group 0;" ::: "memory"); }

// ============================================================
// 0) fp32 -> bf16 weight conversion
// ============================================================
__global__ __launch_bounds__(256)
void cvt_bf(const float4* __restrict__ src, uint2* __restrict__ dst, int n4){
    int i = blockIdx.x*256 + threadIdx.x;
    if (i < n4){
        float4 v = src[i];
        dst[i] = make_uint2(pack_bf(v.x, v.y), pack_bf(v.z, v.w));
    }
}

// ============================================================
// 1) conditional LayerNorm (writes fp32 + bf16 copies)
// ============================================================
__global__ __launch_bounds__(128)
void ln_kernel(const float* __restrict__ x, const int* __restrict__ gt,
               const float* __restrict__ tfg, const float* __restrict__ tfb,
               const float* __restrict__ tgg, const float* __restrict__ tgb) {
    int t = blockIdx.x;
    int tid = threadIdx.x;
    const float4 v = ((const float4*)(x + (size_t)t*DD))[tid];
    float s  = v.x+v.y+v.z+v.w;
    float sq = v.x*v.x+v.y*v.y+v.z*v.z+v.w*v.w;
    #pragma unroll
    for (int o=16;o;o>>=1){ s += __shfl_xor_sync(~0u,s,o); sq += __shfl_xor_sync(~0u,sq,o); }
    __shared__ float sh[8];
    int w = tid>>5, l = tid&31;
    if (l==0){ sh[w]=s; sh[4+w]=sq; }
    __syncthreads();
    if (tid==0){
        float S=sh[0]+sh[1]+sh[2]+sh[3], Q=sh[4]+sh[5]+sh[6]+sh[7];
        float mu = S/(float)DD;
        float var = Q/(float)DD - mu*mu;
        sh[0]=mu; sh[1]=rsqrtf(var + 1e-5f);
    }
    __syncthreads();
    float mu = sh[0], rs = sh[1];
    int g = gt[t];
    float4 out;
    if (g==0 || g==1){
        const float* gp = (g==0)? tfg : tgg;
        const float* bp = (g==0)? tfb : tgb;
        float4 gv = ((const float4*)gp)[tid];
        float4 bv = ((const float4*)bp)[tid];
        out.x = (v.x-mu)*rs*gv.x + bv.x;
        out.y = (v.y-mu)*rs*gv.y + bv.y;
        out.z = (v.z-mu)*rs*gv.z + bv.z;
        out.w = (v.w-mu)*rs*gv.w + bv.w;
    } else {
        out = v;
    }
    ((float4*)(g_xn + (size_t)t*DD))[tid] = out;
    ((uint2*)(g_xnh + (size_t)t*DD))[tid] = make_uint2(pack_bf(out.x,out.y), pack_bf(out.z,out.w));
}

// ============================================================
// 2) bf16 GEMM, cp.async double-buffered: C = A[M,K]·B[N,K]^T
//    128x128 block, 256 threads (8 warps 4x2 -> 32x64 warp tile), BK=32
//    EPI: 0 = bias->Cb ; 1 = bias+res->Cf+Cb ; 2 = SiLU->Cf
// ============================================================
#define GP 40   // smem pitch in halfs (80B, 16B-aligned rows, conflict-free LDSM)
template<int EPI>
__global__ __launch_bounds__(256)
void gemm_bf(const __nv_bfloat16* __restrict__ A, const __nv_bfloat16* __restrict__ B,
             const float* __restrict__ bias, const float* __restrict__ res,
             float* __restrict__ Cf, __nv_bfloat16* __restrict__ Cb, int N, int K) {
    __shared__ __align__(16) __nv_bfloat16 As[2][128*GP];
    __shared__ __align__(16) __nv_bfloat16 Bs[2][128*GP];
    int tid = threadIdx.x;
    int w = tid>>5, lane = tid&31;
    int qr = lane>>2, qc = lane&3;
    int wy = w>>1, wx = w&1;
    int m0 = blockIdx.y*128, n0 = blockIdx.x*128;
    int lr = tid>>1, lh = tid&1;           // loader: row 0..127, 32B half
    int lmr = lane & 15, lmc = lane >> 4;  // ldmatrix addressing

    float acc[2][8][4];
    #pragma unroll
    for (int i=0;i<2;i++)
        #pragma unroll
        for (int j=0;j<8;j++)
            #pragma unroll
            for (int k=0;k<4;k++) acc[i][j][k]=0.f;

    const int NIT = K/32;
    // prologue: tile 0 -> buf 0
    {
        const __nv_bfloat16* ap = A + (size_t)(m0+lr)*K + lh*16;
        const __nv_bfloat16* bp = B + (size_t)(n0+lr)*K + lh*16;
        cpa16(&As[0][lr*GP + lh*16],     ap);
        cpa16(&As[0][lr*GP + lh*16 + 8], ap + 8);
        cpa16(&Bs[0][lr*GP + lh*16],     bp);
        cpa16(&Bs[0][lr*GP + lh*16 + 8], bp + 8);
        cpa_commit();
    }
    for (int it = 0; it < NIT; it++) {
        int cur = it & 1;
        cpa_wait_all();
        __syncthreads();
        if (it+1 < NIT){
            int k0 = (it+1)*32;
            const __nv_bfloat16* ap = A + (size_t)(m0+lr)*K + k0 + lh*16;
            const __nv_bfloat16* bp = B + (size_t)(n0+lr)*K + k0 + lh*16;
            cpa16(&As[cur^1][lr*GP + lh*16],     ap);
            cpa16(&As[cur^1][lr*GP + lh*16 + 8], ap + 8);
            cpa16(&Bs[cur^1][lr*GP + lh*16],     bp);
            cpa16(&Bs[cur^1][lr*GP + lh*16 + 8], bp + 8);
        }
        cpa_commit();
        #pragma unroll
        for (int ks=0; ks<2; ks++) {
            int kb = ks*16;
            unsigned af[2][4], bf[8][2];
            #pragma unroll
            for (int mt=0; mt<2; mt++)
                ldsm4(af[mt][0], af[mt][1], af[mt][2], af[mt][3],
                      &As[cur][(wy*32 + mt*16 + lmr)*GP + kb + lmc*8]);
            #pragma unroll
            for (int ng=0; ng<4; ng++){
                unsigned r0,r1,r2,r3;
                ldsm4(r0,r1,r2,r3, &Bs[cur][(wx*64 + ng*16 + lmr)*GP + kb + lmc*8]);
                bf[2*ng  ][0]=r0; bf[2*ng  ][1]=r2;
                bf[2*ng+1][0]=r1; bf[2*ng+1][1]=r3;
            }
            #pragma unroll
            for (int mt=0; mt<2; mt++)
                #pragma unroll
                for (int nt=0; nt<8; nt++)
                    mma_bf16(acc[mt][nt], af[mt], bf[nt]);
        }
    }
    #pragma unroll
    for (int mt=0; mt<2; mt++){
        #pragma unroll
        for (int nt=0; nt<8; nt++){
            int gr = m0 + wy*32 + mt*16 + qr;
            int gc = n0 + wx*64 + nt*8 + 2*qc;
            float bx = bias[gc], by = bias[gc+1];
            float c0 = acc[mt][nt][0]+bx, c1 = acc[mt][nt][1]+by;
            float c2 = acc[mt][nt][2]+bx, c3 = acc[mt][nt][3]+by;
            if (EPI==0){
                *(unsigned*)(Cb + (size_t)gr*N + gc)     = pack_bf(c0,c1);
                *(unsigned*)(Cb + (size_t)(gr+8)*N + gc) = pack_bf(c2,c3);
            }
            if (EPI==1){
                const float* r0 = res + (size_t)gr*N + gc;
                const float* r1 = res + (size_t)(gr+8)*N + gc;
                c0 += r0[0]; c1 += r0[1]; c2 += r1[0]; c3 += r1[1];
                float2 v0 = {c0,c1}, v1 = {c2,c3};
                *(float2*)(Cf + (size_t)gr*N + gc)     = v0;
                *(float2*)(Cf + (size_t)(gr+8)*N + gc) = v1;
                *(unsigned*)(Cb + (size_t)gr*N + gc)     = pack_bf(c0,c1);
                *(unsigned*)(Cb + (size_t)(gr+8)*N + gc) = pack_bf(c2,c3);
            }
            if (EPI==2){
                c0 = c0/(1.f+__expf(-c0)); c1 = c1/(1.f+__expf(-c1));
                c2 = c2/(1.f+__expf(-c2)); c3 = c3/(1.f+__expf(-c3));
                float2 v0 = {c0,c1}, v1 = {c2,c3};
                *(float2*)(Cf + (size_t)gr*N + gc)     = v0;
                *(float2*)(Cf + (size_t)(gr+8)*N + gc) = v1;
            }
        }
    }
}

// ============================================================
// 3) flash attention: 128 queries/block (8 warps, 16 q rows each),
//    64-key tiles double-buffered via cp.async, P kept in registers
// ============================================================
#define AP 72   // 144B rows (16B-aligned), conflict-free for ldsm patterns
__global__ __launch_bounds__(256)
void attn_bf() {
    __shared__ __align__(16) __nv_bfloat16 Ks[2][64*AP];
    __shared__ __align__(16) __nv_bfloat16 Vs[2][64*AP];
    const __nv_bfloat16* qkv = g_qkv;
    int tid = threadIdx.x;
    int w = tid>>5, lane = tid&31;
    int qr = lane>>2, qc = lane&3;
    int lmr = lane & 15, lmc = lane >> 4;
    int b = blockIdx.y>>3, h = blockIdx.y&7;
    int q0 = blockIdx.x*128;
    size_t base = (size_t)b*SS*QKVD + (size_t)h*HDIM;

    // ---- stage Q (128 rows) through the two buffers, pull frags ----
    {
        int lr = tid>>1, lh = tid&1;   // row 0..127, 64B half
        const uint4* qp = (const uint4*)(qkv + base + (size_t)(q0+lr)*QKVD + lh*32);
        uint4 v0 = qp[0], v1 = qp[1], v2 = qp[2], v3 = qp[3];
        __nv_bfloat16* dst = (lr < 64) ? &Ks[0][lr*AP + lh*32] : &Vs[0][(lr-64)*AP + lh*32];
        uint4* d = (uint4*)dst;
        d[0]=v0; d[1]=v1; d[2]=v2; d[3]=v3;
    }
    __syncthreads();
    unsigned qa[4][4];
    {
        const __nv_bfloat16* qbuf = (w < 4) ? &Ks[0][0] : &Vs[0][0];
        int row16 = (w&3)*16;
        #pragma unroll
        for (int kc=0; kc<4; kc++)
            ldsm4(qa[kc][0], qa[kc][1], qa[kc][2], qa[kc][3],
                  &qbuf[(row16 + lmr)*AP + kc*16 + lmc*8]);
    }
    __syncthreads();

    float o[8][4];
    #pragma unroll
    for (int nt=0; nt<8; nt++){ o[nt][0]=0.f;o[nt][1]=0.f;o[nt][2]=0.f;o[nt][3]=0.f; }
    float m0=-1e30f, m1=-1e30f, l0=0.f, l1=0.f;

    // KV loader split: threads 0..127 -> K, 128..255 -> V
    int kv  = tid >> 7;
    int krow = (tid & 127) >> 1;
    int khalf = tid & 1;
    size_t kvbase = base + (size_t)(1+kv)*DD;

    // prologue: tile 0 -> buf 0
    {
        const __nv_bfloat16* src = qkv + kvbase + (size_t)krow*QKVD + khalf*32;
        __nv_bfloat16* dst = kv ? &Vs[0][krow*AP + khalf*32] : &Ks[0][krow*AP + khalf*32];
        #pragma unroll
        for (int j=0;j<4;j++) cpa16(dst + j*8, src + j*8);
        cpa_commit();
    }

    const int NKT = SS/64;
    for (int kt=0; kt<NKT; kt++){
        int cur = kt & 1;
        cpa_wait_all();
        __syncthreads();
        if (kt+1 < NKT){
            const __nv_bfloat16* src = qkv + kvbase + (size_t)((kt+1)*64 + krow)*QKVD + khalf*32;
            __nv_bfloat16* dst = kv ? &Vs[cur^1][krow*AP + khalf*32] : &Ks[cur^1][krow*AP + khalf*32];
            #pragma unroll
            for (int j=0;j<4;j++) cpa16(dst + j*8, src + j*8);
        }
        cpa_commit();

        // S = Q·K^T (per warp: 16 q x 64 keys)
        float sacc[8][4];
        #pragma unroll
        for (int nt=0; nt<8; nt++){ sacc[nt][0]=0.f;sacc[nt][1]=0.f;sacc[nt][2]=0.f;sacc[nt][3]=0.f; }
        #pragma unroll
        for (int kc=0; kc<4; kc++){
            #pragma unroll
            for (int ng=0; ng<4; ng++){
                unsigned r0,r1,r2,r3;
                ldsm4(r0,r1,r2,r3, &Ks[cur][(ng*16 + lmr)*AP + kc*16 + lmc*8]);
                unsigned bfa[2] = {r0, r2};
                unsigned bfb[2] = {r1, r3};
                mma_bf16(sacc[2*ng  ], qa[kc], bfa);
                mma_bf16(sacc[2*ng+1], qa[kc], bfb);
            }
        }
        // scale + online softmax
        float mx0=-1e30f, mx1=-1e30f;
        #pragma unroll
        for (int nt=0; nt<8; nt++){
            sacc[nt][0]*=0.125f; sacc[nt][1]*=0.125f; sacc[nt][2]*=0.125f; sacc[nt][3]*=0.125f;
            mx0 = fmaxf(mx0, fmaxf(sacc[nt][0], sacc[nt][1]));
            mx1 = fmaxf(mx1, fmaxf(sacc[nt][2], sacc[nt][3]));
        }
        mx0 = fmaxf(mx0, __shfl_xor_sync(~0u, mx0, 1));
        mx0 = fmaxf(mx0, __shfl_xor_sync(~0u, mx0, 2));
        mx1 = fmaxf(mx1, __shfl_xor_sync(~0u, mx1, 1));
        mx1 = fmaxf(mx1, __shfl_xor_sync(~0u, mx1, 2));
        float nm0 = fmaxf(m0, mx0), nm1 = fmaxf(m1, mx1);
        float a0 = __expf(m0 - nm0), a1 = __expf(m1 - nm1);
        float s0 = 0.f, s1 = 0.f;
        #pragma unroll
        for (int nt=0; nt<8; nt++){
            sacc[nt][0] = __expf(sacc[nt][0] - nm0);
            sacc[nt][1] = __expf(sacc[nt][1] - nm0);
            sacc[nt][2] = __expf(sacc[nt][2] - nm1);
            sacc[nt][3] = __expf(sacc[nt][3] - nm1);
            s0 += sacc[nt][0] + sacc[nt][1];
            s1 += sacc[nt][2] + sacc[nt][3];
        }
        s0 += __shfl_xor_sync(~0u, s0, 1); s0 += __shfl_xor_sync(~0u, s0, 2);
        s1 += __shfl_xor_sync(~0u, s1, 1); s1 += __shfl_xor_sync(~0u, s1, 2);
        l0 = l0*a0 + s0; l1 = l1*a1 + s1; m0 = nm0; m1 = nm1;
        #pragma unroll
        for (int nt=0; nt<8; nt++){
            o[nt][0]*=a0; o[nt][1]*=a0; o[nt][2]*=a1; o[nt][3]*=a1;
        }
        // O += P·V : P directly from registers (S-frag == A-frag), V via ldsm.trans
        #pragma unroll
        for (int kc=0; kc<4; kc++){
            unsigned pa[4];
            pa[0] = pack_bf(sacc[2*kc  ][0], sacc[2*kc  ][1]);
            pa[1] = pack_bf(sacc[2*kc  ][2], sacc[2*kc  ][3]);
            pa[2] = pack_bf(sacc[2*kc+1][0], sacc[2*kc+1][1]);
            pa[3] = pack_bf(sacc[2*kc+1][2], sacc[2*kc+1][3]);
            #pragma unroll
            for (int ng=0; ng<4; ng++){
                unsigned r0,r1,r2,r3;
                ldsm4t(r0,r1,r2,r3,
                       &Vs[cur][(kc*16 + ((lane>>3)&1)*8 + (lane&7))*AP + ng*16 + (lane>>4)*8]);
                unsigned bfa[2] = {r0, r1};
                unsigned bfb[2] = {r2, r3};
                mma_bf16(o[2*ng  ], pa, bfa);
                mma_bf16(o[2*ng+1], pa, bfb);
            }
        }
    }
    float i0 = 1.f/l0, i1 = 1.f/l1;
    int sr = q0 + w*16 + qr;
    __nv_bfloat16* op = g_att + (size_t)(b*SS + sr)*DD + h*HDIM;
    #pragma unroll
    for (int nt=0; nt<8; nt++){
        *(unsigned*)(op + nt*8 + 2*qc)        = pack_bf(o[nt][0]*i0, o[nt][1]*i0);
        *(unsigned*)(op + 8*DD + nt*8 + 2*qc) = pack_bf(o[nt][2]*i1, o[nt][3]*i1);
    }
}

// ============================================================
// 4) gate: strength = sigmoid(h . w2 + b2); out = xr * strength
// ============================================================
__global__ __launch_bounds__(128)
void gate_kernel(const float* __restrict__ w2, const float* __restrict__ b2,
                 float* __restrict__ out) {
    int t = blockIdx.x;
    int tid = threadIdx.x;
    const float* hp = g_hid + (size_t)t*(DD/2);
    float part = hp[tid]*w2[tid] + hp[tid+128]*w2[tid+128];
    #pragma unroll
    for (int o=16;o;o>>=1) part += __shfl_xor_sync(~0u, part, o);
    __shared__ float sh[4];
    int w = tid>>5, l = tid&31;
    if (l==0) sh[w] = part;
    __syncthreads();
    float tot = sh[0]+sh[1]+sh[2]+sh[3];
    float sgate = 1.f / (1.f + __expf(-(tot + b2[0])));
    float4 xv = ((const float4*)(g_xr + (size_t)t*DD))[tid];
    float4 ov = { xv.x*sgate, xv.y*sgate, xv.z*sgate, xv.w*sgate };
    ((float4*)out)[(size_t)t*128 + tid] = ov;
}

// ============================================================
extern "C" void kernel_launch(void* const* d_in, const int* in_sizes, int n_in,
                              void* d_out, int out_size) {
    const float* x    = (const float*)d_in[0];
    const int*   gt   = (const int*)  d_in[1];
    const float* tf_g = (const float*)d_in[2];
    const float* tf_b = (const float*)d_in[3];
    const float* tg_g = (const float*)d_in[4];
    const float* tg_b = (const float*)d_in[5];
    const float* Wqkv = (const float*)d_in[6];
    const float* bqkv = (const float*)d_in[7];
    const float* Wo   = (const float*)d_in[8];
    const float* bo   = (const float*)d_in[9];
    const float* W1   = (const float*)d_in[10];
    const float* b1   = (const float*)d_in[11];
    const float* w2   = (const float*)d_in[12];
    const float* b2   = (const float*)d_in[13];
    float* out = (float*)d_out;

    float *xn, *xr, *hid;
    __nv_bfloat16 *xnh, *qkvp, *att, *xrh, *wqkvh, *woh, *w1h;
    cudaGetSymbolAddress((void**)&xn,    g_xn);
    cudaGetSymbolAddress((void**)&xnh,   g_xnh);
    cudaGetSymbolAddress((void**)&qkvp,  g_qkv);
    cudaGetSymbolAddress((void**)&att,   g_att);
    cudaGetSymbolAddress((void**)&xr,    g_xr);
    cudaGetSymbolAddress((void**)&xrh,   g_xrh);
    cudaGetSymbolAddress((void**)&hid,   g_hid);
    cudaGetSymbolAddress((void**)&wqkvh, g_wqkvh);
    cudaGetSymbolAddress((void**)&woh,   g_woh);
    cudaGetSymbolAddress((void**)&w1h,   g_w1h);

    // 0) weight conversions fp32 -> bf16
    cvt_bf<<<(QKVD*DD/4 + 255)/256, 256>>>((const float4*)Wqkv, (uint2*)wqkvh, QKVD*DD/4);
    cvt_bf<<<(DD*DD/4 + 255)/256, 256>>>((const float4*)Wo, (uint2*)woh, DD*DD/4);
    cvt_bf<<<((DD/2)*DD/4 + 255)/256, 256>>>((const float4*)W1, (uint2*)w1h, (DD/2)*DD/4);
    // 1) conditional LayerNorm -> g_xn (fp32) + g_xnh (bf16)
    ln_kernel<<<NT, 128>>>(x, gt, tf_g, tf_b, tg_g, tg_b);
    // 2) QKV projection -> g_qkv (bf16)
    gemm_bf<0><<<dim3(QKVD/128, NT/128), 256>>>(xnh, wqkvh, bqkv, nullptr, nullptr, qkvp, QKVD, DD);
    // 3) flash attention -> g_att (bf16)
    attn_bf<<<dim3(SS/128, BB*HH), 256>>>();
    // 4) out projection + residual -> g_xr (fp32) + g_xrh (bf16)
    gemm_bf<1><<<dim3(DD/128, NT/128), 256>>>(att, woh, bo, xn, xr, xrh, DD, DD);
    // 5) gate hidden: silu(xr @ W1^T + b1) -> g_hid (fp32)
    gemm_bf<2><<<dim3((DD/2)/128, NT/128), 256>>>(xrh, w1h, b1, nullptr, hid, nullptr, DD/2, DD);
    // 6) strength + final scale -> out
    gate_kernel<<<NT, 128>>>(w2, b2, out);
}